// round 6
// baseline (speedup 1.0000x reference)
#include <cuda_runtime.h>
#include <cstdint>

#define CI  256   // channels
#define II  16    // irrep dim
#define NK3 23
#define NK2 4
#define NT3 816   // C(18,3) sorted triples p<=q<=j
#define NT2 136   // sorted pairs p<=q
#define NCOEFF (NT3 + NT2 + II)   // 968
#define BMAX 4096

// ---------------- static device scratch (no allocation allowed) ----------------
__device__ float              g_P[NT3 * NK3];          // symmetrized U3 basis
__device__ unsigned long long g_coeff[CI * 1024];      // per-channel packed (v,v) coeffs
__device__ float              g_out1T[CI * BMAX];      // (C, B) transposed intermediate

typedef unsigned long long ull;

// ---------------- f32x2 packed-math helpers (sm_103a FFMA2 path) ----------------
__device__ __forceinline__ ull pk2(float lo, float hi) {
    ull r;
    asm("mov.b64 %0, {%1, %2};" : "=l"(r) : "f"(lo), "f"(hi));
    return r;
}
__device__ __forceinline__ void upk2(ull v, float& lo, float& hi) {
    asm("mov.b64 {%0, %1}, %2;" : "=f"(lo), "=f"(hi) : "l"(v));
}
__device__ __forceinline__ ull fma2(ull a, ull b, ull c) {
    ull d;
    asm("fma.rn.f32x2 %0, %1, %2, %3;" : "=l"(d) : "l"(a), "l"(b), "l"(c));
    return d;
}

// ---------------- P0: symmetrize U3 over permutations -> g_P[t][k] ----------------
#define U3AT(a, b, d) U3[((((a) * II + (b)) * II + (d)) * NK3) + k]

__global__ void p0_kernel(const float* __restrict__ U3) {
    int idx = blockIdx.x * blockDim.x + threadIdx.x;
    if (idx >= NT3 * NK3) return;
    int t = idx / NK3, k = idx - t * NK3;
    int p = 0, rem = t;
    while (rem >= (II - p) * (II - p + 1) / 2) { rem -= (II - p) * (II - p + 1) / 2; p++; }
    int q = p;
    while (rem >= II - q) { rem -= II - q; q++; }
    int j = q + rem;

    float s;
    if (p == q && q == j) {
        s = U3AT(p, p, p);
    } else if (p == q) {
        s = U3AT(p, p, j) + U3AT(p, j, p) + U3AT(j, p, p);
    } else if (q == j) {
        s = U3AT(p, q, q) + U3AT(q, p, q) + U3AT(q, q, p);
    } else {
        s = U3AT(p, q, j) + U3AT(p, j, q) + U3AT(q, p, j) +
            U3AT(q, j, p) + U3AT(j, p, q) + U3AT(j, q, p);
    }
    g_P[t * NK3 + k] = s;
}

// ---------------- P1: per-channel coefficient build ----------------
__global__ void p1_kernel(const float* __restrict__ U2, const float* __restrict__ U1,
                          const float* __restrict__ w3, const float* __restrict__ w2,
                          const float* __restrict__ w1) {
    int c = blockIdx.x;
    int tid = threadIdx.x;
    __shared__ float w3s[NK3];
    __shared__ float w2s[NK2];
    __shared__ float w1s;
    if (tid < NK3) w3s[tid] = w3[c * NK3 + tid];
    if (tid < NK2) w2s[tid] = w2[c * NK2 + tid];
    if (tid == 0)  w1s = w1[c];
    __syncthreads();

    ull* cc = g_coeff + (size_t)c * 1024;

    for (int t = tid; t < NT3; t += blockDim.x) {
        float s = 0.f;
#pragma unroll
        for (int k = 0; k < NK3; k++) s += g_P[t * NK3 + k] * w3s[k];
        cc[t] = pk2(s, s);
    }
    for (int u = tid; u < NT2; u += blockDim.x) {
        int p = 0, rem = u;
        while (rem >= II - p) { rem -= II - p; p++; }
        int q = p + rem;
        float s = 0.f;
#pragma unroll
        for (int k = 0; k < NK2; k++) {
            float v = (p == q) ? U2[(p * II + p) * NK2 + k]
                               : (U2[(p * II + q) * NK2 + k] + U2[(q * II + p) * NK2 + k]);
            s += w2s[k] * v;
        }
        cc[NT3 + u] = pk2(s, s);
    }
    for (int p = tid; p < II; p += blockDim.x) {
        float s = U1[p] * w1s;  // K1 == 1
        cc[NT3 + NT2 + p] = pk2(s, s);
    }
}

// ---------------- Main: factored contraction, 8 b's/thread, 64-thread CTAs ----------------
#define XPAD 524   // row stride (floats): multiple of 4 (16B align), 524%32=12 spreads banks
__global__ __launch_bounds__(64) void main_kernel(const float* __restrict__ nf) {
    __shared__ ull   sco[NCOEFF];           // 7.75 KB
    __shared__ float xs[II][XPAD];          // 33.5 KB transposed x tile (512 b's)
    int c = blockIdx.y;
    int tid = threadIdx.x;
    {
        const ull* cc = g_coeff + (size_t)c * 1024;
        for (int i = tid; i < NCOEFF; i += 64) sco[i] = cc[i];
    }
    int bbase = blockIdx.x * 512;

    // cooperative load of x tile: 512 rows x 16 floats, transposed into xs[i][r]
#pragma unroll
    for (int it = 0; it < 32; it++) {
        int f = it * 64 + tid;
        int r = f >> 2, qd = f & 3;
        float4 v = *reinterpret_cast<const float4*>(
            &nf[((size_t)(bbase + r) * CI + c) * II + qd * 4]);
        xs[qd * 4 + 0][r] = v.x;
        xs[qd * 4 + 1][r] = v.y;
        xs[qd * 4 + 2][r] = v.z;
        xs[qd * 4 + 3][r] = v.w;
    }
    __syncthreads();

    // per-thread x: 8 consecutive b's as 4 packed pairs A,B,C,D
    int t8 = tid * 8;
    ull xA[II], xB[II], xC[II], xD[II];
#pragma unroll
    for (int i = 0; i < II; i++) {
        float4 v0 = *reinterpret_cast<const float4*>(&xs[i][t8]);
        float4 v1 = *reinterpret_cast<const float4*>(&xs[i][t8 + 4]);
        xA[i] = pk2(v0.x, v0.y);
        xB[i] = pk2(v0.z, v0.w);
        xC[i] = pk2(v1.x, v1.y);
        xD[i] = pk2(v1.z, v1.w);
    }

    // out = sum_p x_p * ( c1_p + sum_{q>=p} x_q * ( c2_pq + sum_{j>=q} c3_pqj x_j ) )
    ull accA = 0ull, accB = 0ull, accC = 0ull, accD = 0ull;
    int s = 0, u = 0;     // constant-folded by full unroll
#pragma unroll
    for (int p = 0; p < II; p++) {
        ull c1v = sco[NT3 + NT2 + p];
        ull inA = c1v, inB = c1v, inC = c1v, inD = c1v;
#pragma unroll
        for (int q = p; q < II; q++) {
            ull c2v = sco[NT3 + u]; u++;
            ull pA = c2v, pB = c2v, pC = c2v, pD = c2v;
#pragma unroll
            for (int j = q; j < II; j++) {
                ull sv = sco[s]; s++;
                pA = fma2(xA[j], sv, pA);
                pB = fma2(xB[j], sv, pB);
                pC = fma2(xC[j], sv, pC);
                pD = fma2(xD[j], sv, pD);
            }
            inA = fma2(xA[q], pA, inA);
            inB = fma2(xB[q], pB, inB);
            inC = fma2(xC[q], pC, inC);
            inD = fma2(xD[q], pD, inD);
        }
        accA = fma2(xA[p], inA, accA);
        accB = fma2(xB[p], inB, accB);
        accC = fma2(xC[p], inC, accC);
        accD = fma2(xD[p], inD, accD);
    }

    // coalesced transposed store: g_out1T[c][bbase + 8*tid .. +7]
    float r0, r1, r2, r3, r4, r5, r6, r7;
    upk2(accA, r0, r1); upk2(accB, r2, r3);
    upk2(accC, r4, r5); upk2(accD, r6, r7);
    float* o = &g_out1T[(size_t)c * BMAX + bbase + t8];
    *reinterpret_cast<float4*>(o)     = make_float4(r0, r1, r2, r3);
    *reinterpret_cast<float4*>(o + 4) = make_float4(r4, r5, r6, r7);
}

// ---------------- o3.Linear: 64m x 32n CTA tile, 4m x 4n threads, f32x2 ----------------
__global__ __launch_bounds__(128) void lin_kernel(const float* __restrict__ W,
                                                  float* __restrict__ O) {
    __shared__ __align__(16) ull   As[32][66];   // [kk][m] dup (a,a) pairs, 16.5 KB
    __shared__ __align__(16) float Bs[32][36];   // [kk][n],  4.5 KB

    int mb = blockIdx.x * 64, nb = blockIdx.y * 32;
    int tid = threadIdx.x;
    int tx = tid & 7;       // n quad (8 x 4n = 32n)
    int ty = tid >> 3;      // m quad (16 x 4m = 64m)

    ull acc[4][2] = {};     // [mi][n-pair]

    for (int k0 = 0; k0 < CI; k0 += 32) {
        // stage A: 32k x 64m from transposed intermediate (coalesced along m)
#pragma unroll
        for (int i = 0; i < 4; i++) {
            int f = tid + i * 128;
            int kk = f >> 4, m4 = (f & 15) * 4;
            float4 v = *reinterpret_cast<const float4*>(
                &g_out1T[(size_t)(k0 + kk) * BMAX + mb + m4]);
            As[kk][m4 + 0] = pk2(v.x, v.x);
            As[kk][m4 + 1] = pk2(v.y, v.y);
            As[kk][m4 + 2] = pk2(v.z, v.z);
            As[kk][m4 + 3] = pk2(v.w, v.w);
        }
        // stage B: 32k x 32n of W (coalesced)
#pragma unroll
        for (int i = 0; i < 2; i++) {
            int f = tid + i * 128;
            int kk = f >> 3, n4 = (f & 7) * 4;
            *reinterpret_cast<float4*>(&Bs[kk][n4]) =
                *reinterpret_cast<const float4*>(&W[(size_t)(k0 + kk) * CI + nb + n4]);
        }
        __syncthreads();
#pragma unroll
        for (int kk = 0; kk < 32; kk++) {
            ulonglong2 a01 = *reinterpret_cast<const ulonglong2*>(&As[kk][ty * 4]);
            ulonglong2 a23 = *reinterpret_cast<const ulonglong2*>(&As[kk][ty * 4 + 2]);
            ulonglong2 b   = *reinterpret_cast<const ulonglong2*>(&Bs[kk][tx * 4]);
            acc[0][0] = fma2(a01.x, b.x, acc[0][0]);
            acc[0][1] = fma2(a01.x, b.y, acc[0][1]);
            acc[1][0] = fma2(a01.y, b.x, acc[1][0]);
            acc[1][1] = fma2(a01.y, b.y, acc[1][1]);
            acc[2][0] = fma2(a23.x, b.x, acc[2][0]);
            acc[2][1] = fma2(a23.x, b.y, acc[2][1]);
            acc[3][0] = fma2(a23.y, b.x, acc[3][0]);
            acc[3][1] = fma2(a23.y, b.y, acc[3][1]);
        }
        __syncthreads();
    }

    const float inv = 0.0625f;  // 1/sqrt(256)
#pragma unroll
    for (int mi = 0; mi < 4; mi++) {
        float r[4];
        upk2(acc[mi][0], r[0], r[1]);
        upk2(acc[mi][1], r[2], r[3]);
        float* o = &O[(size_t)(mb + ty * 4 + mi) * CI + nb + tx * 4];
        *reinterpret_cast<float4*>(o) =
            make_float4(r[0] * inv, r[1] * inv, r[2] * inv, r[3] * inv);
    }
}

// ---------------- launch ----------------
extern "C" void kernel_launch(void* const* d_in, const int* in_sizes, int n_in,
                              void* d_out, int out_size) {
    const float* nf = (const float*)d_in[0];
    const float* U3 = (const float*)d_in[1];
    const float* U2 = (const float*)d_in[2];
    const float* U1 = (const float*)d_in[3];
    const float* w3 = (const float*)d_in[4];
    const float* w2 = (const float*)d_in[5];
    const float* w1 = (const float*)d_in[6];
    const float* WL = (const float*)d_in[7];
    float* out = (float*)d_out;

    int B = in_sizes[0] / (CI * II);   // 4096

    p0_kernel<<<(NT3 * NK3 + 255) / 256, 256>>>(U3);
    p1_kernel<<<CI, 128>>>(U2, U1, w3, w2, w1);
    main_kernel<<<dim3(B / 512, CI), 64>>>(nf);
    lin_kernel<<<dim3(B / 64, CI / 32), 128>>>(WL, out);
}

// round 8
// speedup vs baseline: 1.0949x; 1.0949x over previous
#include <cuda_runtime.h>
#include <cstdint>

#define CI  256   // channels
#define II  16    // irrep dim
#define NK3 23
#define NK2 4
#define NT3 816   // C(18,3) sorted triples p<=q<=j (compact count)
#define NT3P 888  // padded: each (p,q) j-run rounded up to even length
#define NT2 136   // sorted pairs p<=q
#define CSTRIDE 1040  // per-channel ull stride: 888 + 136 + 16
#define BMAX 4096

// ---------------- static device scratch (no allocation allowed) ----------------
__device__ float              g_P[NT3 * NK3];          // symmetrized U3 basis
__device__ unsigned long long g_coeff[CI * CSTRIDE];   // per-channel packed (v,v) coeffs
__device__ float              g_out1T[CI * BMAX];      // (C, B) transposed intermediate

typedef unsigned long long ull;

// ---------------- f32x2 packed-math helpers (sm_103a FFMA2 path) ----------------
__device__ __forceinline__ ull pk2(float lo, float hi) {
    ull r;
    asm("mov.b64 %0, {%1, %2};" : "=l"(r) : "f"(lo), "f"(hi));
    return r;
}
__device__ __forceinline__ void upk2(ull v, float& lo, float& hi) {
    asm("mov.b64 {%0, %1}, %2;" : "=f"(lo), "=f"(hi) : "l"(v));
}
__device__ __forceinline__ ull fma2(ull a, ull b, ull c) {
    ull d;
    asm("fma.rn.f32x2 %0, %1, %2, %3;" : "=l"(d) : "l"(a), "l"(b), "l"(c));
    return d;
}

// ---------------- P0: symmetrize U3 over permutations -> g_P[t][k] ----------------
#define U3AT(a, b, d) U3[((((a) * II + (b)) * II + (d)) * NK3) + k]

__global__ void p0_kernel(const float* __restrict__ U3) {
    int idx = blockIdx.x * blockDim.x + threadIdx.x;
    if (idx >= NT3 * NK3) return;
    int t = idx / NK3, k = idx - t * NK3;
    int p = 0, rem = t;
    while (rem >= (II - p) * (II - p + 1) / 2) { rem -= (II - p) * (II - p + 1) / 2; p++; }
    int q = p;
    while (rem >= II - q) { rem -= II - q; q++; }
    int j = q + rem;

    float s;
    if (p == q && q == j) {
        s = U3AT(p, p, p);
    } else if (p == q) {
        s = U3AT(p, p, j) + U3AT(p, j, p) + U3AT(j, p, p);
    } else if (q == j) {
        s = U3AT(p, q, q) + U3AT(q, p, q) + U3AT(q, q, p);
    } else {
        s = U3AT(p, q, j) + U3AT(p, j, q) + U3AT(q, p, j) +
            U3AT(q, j, p) + U3AT(j, p, q) + U3AT(j, q, p);
    }
    g_P[t * NK3 + k] = s;
}

// ---------------- P1: per-channel coefficient build (padded-run layout) ----------------
__global__ void p1_kernel(const float* __restrict__ U2, const float* __restrict__ U1,
                          const float* __restrict__ w3, const float* __restrict__ w2,
                          const float* __restrict__ w1) {
    int c = blockIdx.x;
    int tid = threadIdx.x;
    __shared__ float w3s[NK3];
    __shared__ float w2s[NK2];
    __shared__ float w1s;
    if (tid < NK3) w3s[tid] = w3[c * NK3 + tid];
    if (tid < NK2) w2s[tid] = w2[c * NK2 + tid];
    if (tid == 0)  w1s = w1[c];
    __syncthreads();

    ull* cc = g_coeff + (size_t)c * CSTRIDE;

    // each thread handles one (p,q) run (NT2 = 136 <= 256 threads)
    if (tid < NT2) {
        int r = tid;
        int p = 0, rem = r;
        while (rem >= II - p) { rem -= II - p; p++; }
        int q = p + rem;
        // compact triple start index
        int t0 = 0;
        for (int pp = 0; pp < p; pp++) t0 += (II - pp) * (II - pp + 1) / 2;
        for (int qq = p; qq < q; qq++) t0 += II - qq;
        // padded start index (even)
        int s0 = 0;
        for (int pp = 0; pp < p; pp++)
            for (int qq = pp; qq < II; qq++) s0 += (II - qq + 1) & ~1;
        for (int qq = p; qq < q; qq++) s0 += (II - qq + 1) & ~1;

        int len = II - q;
        for (int l = 0; l < len; l++) {
            float s = 0.f;
#pragma unroll
            for (int k = 0; k < NK3; k++) s += g_P[(t0 + l) * NK3 + k] * w3s[k];
            cc[s0 + l] = pk2(s, s);
        }
        if (len & 1) cc[s0 + len] = 0ull;   // pad slot (never used in fma)

        // c2 for this run
        float s2 = 0.f;
#pragma unroll
        for (int k = 0; k < NK2; k++) {
            float v = (p == q) ? U2[(p * II + p) * NK2 + k]
                               : (U2[(p * II + q) * NK2 + k] + U2[(q * II + p) * NK2 + k]);
            s2 += w2s[k] * v;
        }
        cc[NT3P + r] = pk2(s2, s2);
    }
    if (tid < II) {
        float s = U1[tid] * w1s;  // K1 == 1
        cc[NT3P + NT2 + tid] = pk2(s, s);
    }
}

// ---------------- Main: factored contraction, 4 b's/thread, paired coeff LDS.128 ----------------
#define XPAD 524   // row stride (floats): multiple of 4 (16B align)
__global__ __launch_bounds__(128, 4) void main_kernel(const float* __restrict__ nf) {
    __shared__ __align__(16) ull   sco[CSTRIDE];   // 8.3 KB
    __shared__ float xs[II][XPAD];                 // 33.5 KB transposed x tile (512 b's)
    int c = blockIdx.y;
    int tid = threadIdx.x;
    {
        const ull* cc = g_coeff + (size_t)c * CSTRIDE;
        for (int i = tid; i < CSTRIDE; i += 128) sco[i] = cc[i];
    }
    int bbase = blockIdx.x * 512;

    // cooperative load of x tile: 512 rows x 16 floats, transposed into xs[i][r]
#pragma unroll
    for (int it = 0; it < 16; it++) {
        int f = it * 128 + tid;
        int r = f >> 2, qd = f & 3;
        float4 v = *reinterpret_cast<const float4*>(
            &nf[((size_t)(bbase + r) * CI + c) * II + qd * 4]);
        xs[qd * 4 + 0][r] = v.x;
        xs[qd * 4 + 1][r] = v.y;
        xs[qd * 4 + 2][r] = v.z;
        xs[qd * 4 + 3][r] = v.w;
    }
    __syncthreads();

    // per-thread x: 4 consecutive b's, packed as f32x2 pairs (A = b0,b1; B = b2,b3)
    int t4 = tid * 4;
    ull xA[II], xB[II];
#pragma unroll
    for (int i = 0; i < II; i++) {
        float4 v = *reinterpret_cast<const float4*>(&xs[i][t4]);
        xA[i] = pk2(v.x, v.y);
        xB[i] = pk2(v.z, v.w);
    }

    // out = sum_p x_p * ( c1_p + sum_{q>=p} x_q * ( c2_pq + sum_{j>=q} c3_pqj x_j ) )
    // c3 coefficients consumed 2-at-a-time via 16B LDS (runs stored even-padded)
    ull accA = 0ull, accB = 0ull;
    int s = 0, u = 0;     // constant-folded by full unroll
#pragma unroll
    for (int p = 0; p < II; p++) {
        ull c1v = sco[NT3P + NT2 + p];
        ull inA = c1v, inB = c1v;
#pragma unroll
        for (int q = p; q < II; q++) {
            ull c2v = sco[NT3P + u]; u++;
            ull pA = c2v, pB = c2v;
            const int len = II - q;
            const int pairs = len >> 1;
#pragma unroll
            for (int jj = 0; jj < pairs; jj++) {
                ulonglong2 v = *reinterpret_cast<const ulonglong2*>(&sco[s + 2 * jj]);
                const int j0 = q + 2 * jj;
                pA = fma2(xA[j0], v.x, pA);
                pB = fma2(xB[j0], v.x, pB);
                pA = fma2(xA[j0 + 1], v.y, pA);
                pB = fma2(xB[j0 + 1], v.y, pB);
            }
            if (len & 1) {                       // tail j == II-1 (odd-length run)
                ull sv = sco[s + len - 1];
                pA = fma2(xA[II - 1], sv, pA);
                pB = fma2(xB[II - 1], sv, pB);
            }
            s += (len + 1) & ~1;                 // advance over padded run
            inA = fma2(xA[q], pA, inA);
            inB = fma2(xB[q], pB, inB);
        }
        accA = fma2(xA[p], inA, accA);
        accB = fma2(xB[p], inB, accB);
    }

    // coalesced transposed store: g_out1T[c][bbase + 4*tid .. +3]
    float r0, r1, r2, r3;
    upk2(accA, r0, r1);
    upk2(accB, r2, r3);
    *reinterpret_cast<float4*>(&g_out1T[(size_t)c * BMAX + bbase + t4]) =
        make_float4(r0, r1, r2, r3);
}

// ---------------- o3.Linear: 32m x 32n tiles, k-stage 64 (R5 best measured config) ----------------
__global__ __launch_bounds__(128) void lin_kernel(const float* __restrict__ W,
                                                  float* __restrict__ O) {
    __shared__ __align__(16) ull   As[64][34];   // [kk][m] dup (a,a) pairs, 17.4 KB
    __shared__ __align__(16) float Bs[64][36];   // [kk][n],  9.2 KB

    int mb = blockIdx.x * 32, nb = blockIdx.y * 32;
    int tid = threadIdx.x;
    int tx = tid & 7;       // n quad (8)
    int ty = tid >> 3;      // m pair (16)

    ull acc[2][2] = {};     // [mi][n-pair]

    for (int k0 = 0; k0 < CI; k0 += 64) {
        // stage A: 64k x 32m from transposed intermediate (coalesced along m)
#pragma unroll
        for (int i = 0; i < 4; i++) {
            int f = tid + i * 128;
            int kk = f >> 3, m4 = (f & 7) * 4;
            float4 v = *reinterpret_cast<const float4*>(
                &g_out1T[(size_t)(k0 + kk) * BMAX + mb + m4]);
            As[kk][m4 + 0] = pk2(v.x, v.x);
            As[kk][m4 + 1] = pk2(v.y, v.y);
            As[kk][m4 + 2] = pk2(v.z, v.z);
            As[kk][m4 + 3] = pk2(v.w, v.w);
        }
        // stage B: 64k x 32n of W (coalesced) — i<4 covers kk 0..63 (R7 bug: i<2)
#pragma unroll
        for (int i = 0; i < 4; i++) {
            int f = tid + i * 128;
            int kk = f >> 3, n4 = (f & 7) * 4;
            *reinterpret_cast<float4*>(&Bs[kk][n4]) =
                *reinterpret_cast<const float4*>(&W[(size_t)(k0 + kk) * CI + nb + n4]);
        }
        __syncthreads();
#pragma unroll
        for (int kk = 0; kk < 64; kk++) {
            ulonglong2 a = *reinterpret_cast<const ulonglong2*>(&As[kk][ty * 2]);
            ulonglong2 b = *reinterpret_cast<const ulonglong2*>(&Bs[kk][tx * 4]);
            acc[0][0] = fma2(a.x, b.x, acc[0][0]);
            acc[0][1] = fma2(a.x, b.y, acc[0][1]);
            acc[1][0] = fma2(a.y, b.x, acc[1][0]);
            acc[1][1] = fma2(a.y, b.y, acc[1][1]);
        }
        __syncthreads();
    }

    const float inv = 0.0625f;  // 1/sqrt(256)
#pragma unroll
    for (int mi = 0; mi < 2; mi++) {
        float r[4];
        upk2(acc[mi][0], r[0], r[1]);
        upk2(acc[mi][1], r[2], r[3]);
        float* o = &O[(size_t)(mb + ty * 2 + mi) * CI + nb + tx * 4];
        *reinterpret_cast<float4*>(o) =
            make_float4(r[0] * inv, r[1] * inv, r[2] * inv, r[3] * inv);
    }
}

// ---------------- launch ----------------
extern "C" void kernel_launch(void* const* d_in, const int* in_sizes, int n_in,
                              void* d_out, int out_size) {
    const float* nf = (const float*)d_in[0];
    const float* U3 = (const float*)d_in[1];
    const float* U2 = (const float*)d_in[2];
    const float* U1 = (const float*)d_in[3];
    const float* w3 = (const float*)d_in[4];
    const float* w2 = (const float*)d_in[5];
    const float* w1 = (const float*)d_in[6];
    const float* WL = (const float*)d_in[7];
    float* out = (float*)d_out;

    int B = in_sizes[0] / (CI * II);   // 4096

    p0_kernel<<<(NT3 * NK3 + 255) / 256, 256>>>(U3);
    p1_kernel<<<CI, 256>>>(U2, U1, w3, w2, w1);
    main_kernel<<<dim3(B / 512, CI), 128>>>(nf);
    lin_kernel<<<dim3(B / 32, CI / 32), 128>>>(WL, out);
}

// round 9
// speedup vs baseline: 1.1877x; 1.0848x over previous
#include <cuda_runtime.h>
#include <cstdint>

#define CI  256   // channels
#define II  16    // irrep dim
#define NK3 23
#define NK2 4
#define NT3 816   // C(18,3) sorted triples p<=q<=j
#define NT2 136   // sorted pairs p<=q
#define NCOEFF (NT3 + NT2 + II)   // 968
#define BMAX 4096

// ---------------- static device scratch (no allocation allowed) ----------------
__device__ float              g_P[NT3 * NK3];          // symmetrized U3 basis
__device__ unsigned long long g_coeff[CI * 1024];      // per-channel packed (v,v) coeffs
__device__ float              g_out1T[CI * BMAX];      // (C, B) transposed intermediate

typedef unsigned long long ull;

// ---------------- f32x2 packed-math helpers (sm_103a FFMA2 path) ----------------
__device__ __forceinline__ ull pk2(float lo, float hi) {
    ull r;
    asm("mov.b64 %0, {%1, %2};" : "=l"(r) : "f"(lo), "f"(hi));
    return r;
}
__device__ __forceinline__ void upk2(ull v, float& lo, float& hi) {
    asm("mov.b64 {%0, %1}, %2;" : "=f"(lo), "=f"(hi) : "l"(v));
}
__device__ __forceinline__ ull fma2(ull a, ull b, ull c) {
    ull d;
    asm("fma.rn.f32x2 %0, %1, %2, %3;" : "=l"(d) : "l"(a), "l"(b), "l"(c));
    return d;
}

// ---------------- P0: symmetrize U3 over permutations -> g_P[t][k] ----------------
#define U3AT(a, b, d) U3[((((a) * II + (b)) * II + (d)) * NK3) + k]

__global__ void p0_kernel(const float* __restrict__ U3) {
    int idx = blockIdx.x * blockDim.x + threadIdx.x;
    if (idx >= NT3 * NK3) return;
    int t = idx / NK3, k = idx - t * NK3;
    int p = 0, rem = t;
    while (rem >= (II - p) * (II - p + 1) / 2) { rem -= (II - p) * (II - p + 1) / 2; p++; }
    int q = p;
    while (rem >= II - q) { rem -= II - q; q++; }
    int j = q + rem;

    float s;
    if (p == q && q == j) {
        s = U3AT(p, p, p);
    } else if (p == q) {
        s = U3AT(p, p, j) + U3AT(p, j, p) + U3AT(j, p, p);
    } else if (q == j) {
        s = U3AT(p, q, q) + U3AT(q, p, q) + U3AT(q, q, p);
    } else {
        s = U3AT(p, q, j) + U3AT(p, j, q) + U3AT(q, p, j) +
            U3AT(q, j, p) + U3AT(j, p, q) + U3AT(j, q, p);
    }
    g_P[t * NK3 + k] = s;
}

// ---------------- P1: per-channel coefficient build (compact layout) ----------------
__global__ void p1_kernel(const float* __restrict__ U2, const float* __restrict__ U1,
                          const float* __restrict__ w3, const float* __restrict__ w2,
                          const float* __restrict__ w1) {
    int c = blockIdx.x;
    int tid = threadIdx.x;
    __shared__ float w3s[NK3];
    __shared__ float w2s[NK2];
    __shared__ float w1s;
    if (tid < NK3) w3s[tid] = w3[c * NK3 + tid];
    if (tid < NK2) w2s[tid] = w2[c * NK2 + tid];
    if (tid == 0)  w1s = w1[c];
    __syncthreads();

    ull* cc = g_coeff + (size_t)c * 1024;

    for (int t = tid; t < NT3; t += blockDim.x) {
        float s = 0.f;
#pragma unroll
        for (int k = 0; k < NK3; k++) s += g_P[t * NK3 + k] * w3s[k];
        cc[t] = pk2(s, s);
    }
    for (int u = tid; u < NT2; u += blockDim.x) {
        int p = 0, rem = u;
        while (rem >= II - p) { rem -= II - p; p++; }
        int q = p + rem;
        float s = 0.f;
#pragma unroll
        for (int k = 0; k < NK2; k++) {
            float v = (p == q) ? U2[(p * II + p) * NK2 + k]
                               : (U2[(p * II + q) * NK2 + k] + U2[(q * II + p) * NK2 + k]);
            s += w2s[k] * v;
        }
        cc[NT3 + u] = pk2(s, s);
    }
    for (int p = tid; p < II; p += blockDim.x) {
        float s = U1[p] * w1s;  // K1 == 1
        cc[NT3 + NT2 + p] = pk2(s, s);
    }
}

// ---------------- Main: factored symmetric contraction, staged x, 4 b's/thread ----------------
#define XPAD 524   // row stride (floats): mult of 4 for 16B align
__global__ __launch_bounds__(128, 4) void main_kernel(const float* __restrict__ nf) {
    __shared__ ull   sco[NCOEFF];           // 7.75 KB
    __shared__ float xs[II][XPAD];          // 33.5 KB transposed x tile (512 b's)
    int c = blockIdx.y;
    int tid = threadIdx.x;
    {
        const ull* cc = g_coeff + (size_t)c * 1024;
        for (int i = tid; i < NCOEFF; i += 128) sco[i] = cc[i];
    }
    int bbase = blockIdx.x * 512;

    // cooperative load of x tile: 512 rows x 16 floats, transposed into xs[i][r]
#pragma unroll
    for (int it = 0; it < 16; it++) {
        int f = it * 128 + tid;
        int r = f >> 2, qd = f & 3;
        float4 v = *reinterpret_cast<const float4*>(
            &nf[((size_t)(bbase + r) * CI + c) * II + qd * 4]);
        xs[qd * 4 + 0][r] = v.x;
        xs[qd * 4 + 1][r] = v.y;
        xs[qd * 4 + 2][r] = v.z;
        xs[qd * 4 + 3][r] = v.w;
    }
    __syncthreads();

    // per-thread x: 4 consecutive b's, packed as f32x2 pairs (A = b0,b1; B = b2,b3)
    int t4 = tid * 4;
    ull xA[II], xB[II];
#pragma unroll
    for (int i = 0; i < II; i++) {
        float4 v = *reinterpret_cast<const float4*>(&xs[i][t4]);
        xA[i] = pk2(v.x, v.y);
        xB[i] = pk2(v.z, v.w);
    }

    // out = sum_p x_p * ( c1_p + sum_{q>=p} x_q * ( c2_pq + sum_{j>=q} c3_pqj x_j ) )
    ull accA = 0ull, accB = 0ull;
    int s = 0, u = 0;     // constant-folded by full unroll
#pragma unroll
    for (int p = 0; p < II; p++) {
        ull c1v = sco[NT3 + NT2 + p];
        ull innerA = c1v, innerB = c1v;
#pragma unroll
        for (int q = p; q < II; q++) {
            ull c2v = sco[NT3 + u]; u++;
            ull pA = c2v, pB = c2v;
#pragma unroll
            for (int j = q; j < II; j++) {
                ull sv = sco[s]; s++;
                pA = fma2(xA[j], sv, pA);
                pB = fma2(xB[j], sv, pB);
            }
            innerA = fma2(xA[q], pA, innerA);
            innerB = fma2(xB[q], pB, innerB);
        }
        accA = fma2(xA[p], innerA, accA);
        accB = fma2(xB[p], innerB, accB);
    }

    // coalesced transposed store: g_out1T[c][bbase + 4*tid .. +3]
    float r0, r1, r2, r3;
    upk2(accA, r0, r1);
    upk2(accB, r2, r3);
    *reinterpret_cast<float4*>(&g_out1T[(size_t)c * BMAX + bbase + t4]) =
        make_float4(r0, r1, r2, r3);
}

// ---------------- o3.Linear: 32m x 32n tiles, double-buffered software pipeline ----------------
__global__ __launch_bounds__(128) void lin_kernel(const float* __restrict__ W,
                                                  float* __restrict__ O) {
    __shared__ __align__(16) ull   As[2][32][32];   // [buf][kk][m] dup (a,a), 16.4 KB
    __shared__ __align__(16) float Bs[2][32][32];   // [buf][kk][n] raw,       8.2 KB

    int mb = blockIdx.x * 32, nb = blockIdx.y * 32;
    int tid = threadIdx.x;
    int tx = tid & 7;       // n quad (8 x 4n = 32n)
    int ty = tid >> 3;      // m pair (16 x 2m = 32m)

    // per-thread staging slots: 2 float4 per operand per stage
    int kk0 = tid >> 3,        c40 = (tid & 7) * 4;
    int kk1 = (tid >> 3) + 16, c41 = (tid & 7) * 4;

    float4 ra0, ra1, rb0, rb1;

    // prologue: load + store stage 0
    ra0 = *reinterpret_cast<const float4*>(&g_out1T[(size_t)kk0 * BMAX + mb + c40]);
    ra1 = *reinterpret_cast<const float4*>(&g_out1T[(size_t)kk1 * BMAX + mb + c41]);
    rb0 = *reinterpret_cast<const float4*>(&W[(size_t)kk0 * CI + nb + c40]);
    rb1 = *reinterpret_cast<const float4*>(&W[(size_t)kk1 * CI + nb + c41]);
    {
        ulonglong2 d;
        d.x = pk2(ra0.x, ra0.x); d.y = pk2(ra0.y, ra0.y);
        *reinterpret_cast<ulonglong2*>(&As[0][kk0][c40]) = d;
        d.x = pk2(ra0.z, ra0.z); d.y = pk2(ra0.w, ra0.w);
        *reinterpret_cast<ulonglong2*>(&As[0][kk0][c40 + 2]) = d;
        d.x = pk2(ra1.x, ra1.x); d.y = pk2(ra1.y, ra1.y);
        *reinterpret_cast<ulonglong2*>(&As[0][kk1][c41]) = d;
        d.x = pk2(ra1.z, ra1.z); d.y = pk2(ra1.w, ra1.w);
        *reinterpret_cast<ulonglong2*>(&As[0][kk1][c41 + 2]) = d;
        *reinterpret_cast<float4*>(&Bs[0][kk0][c40]) = rb0;
        *reinterpret_cast<float4*>(&Bs[0][kk1][c41]) = rb1;
    }
    __syncthreads();

    ull acc[2][2] = {};     // [mi][n-pair]

#pragma unroll
    for (int stg = 0; stg < 8; stg++) {
        const int buf = stg & 1;
        if (stg < 7) {      // issue next-stage loads; latency hidden behind compute
            int k0 = (stg + 1) * 32;
            ra0 = *reinterpret_cast<const float4*>(&g_out1T[(size_t)(k0 + kk0) * BMAX + mb + c40]);
            ra1 = *reinterpret_cast<const float4*>(&g_out1T[(size_t)(k0 + kk1) * BMAX + mb + c41]);
            rb0 = *reinterpret_cast<const float4*>(&W[(size_t)(k0 + kk0) * CI + nb + c40]);
            rb1 = *reinterpret_cast<const float4*>(&W[(size_t)(k0 + kk1) * CI + nb + c41]);
        }
#pragma unroll
        for (int kk = 0; kk < 32; kk++) {
            ulonglong2 a = *reinterpret_cast<const ulonglong2*>(&As[buf][kk][ty * 2]);
            ulonglong2 b = *reinterpret_cast<const ulonglong2*>(&Bs[buf][kk][tx * 4]);
            acc[0][0] = fma2(a.x, b.x, acc[0][0]);
            acc[0][1] = fma2(a.x, b.y, acc[0][1]);
            acc[1][0] = fma2(a.y, b.x, acc[1][0]);
            acc[1][1] = fma2(a.y, b.y, acc[1][1]);
        }
        if (stg < 7) {
            const int nbuf = buf ^ 1;   // readers of nbuf finished before last sync
            ulonglong2 d;
            d.x = pk2(ra0.x, ra0.x); d.y = pk2(ra0.y, ra0.y);
            *reinterpret_cast<ulonglong2*>(&As[nbuf][kk0][c40]) = d;
            d.x = pk2(ra0.z, ra0.z); d.y = pk2(ra0.w, ra0.w);
            *reinterpret_cast<ulonglong2*>(&As[nbuf][kk0][c40 + 2]) = d;
            d.x = pk2(ra1.x, ra1.x); d.y = pk2(ra1.y, ra1.y);
            *reinterpret_cast<ulonglong2*>(&As[nbuf][kk1][c41]) = d;
            d.x = pk2(ra1.z, ra1.z); d.y = pk2(ra1.w, ra1.w);
            *reinterpret_cast<ulonglong2*>(&As[nbuf][kk1][c41 + 2]) = d;
            *reinterpret_cast<float4*>(&Bs[nbuf][kk0][c40]) = rb0;
            *reinterpret_cast<float4*>(&Bs[nbuf][kk1][c41]) = rb1;
        }
        __syncthreads();
    }

    const float inv = 0.0625f;  // 1/sqrt(256)
#pragma unroll
    for (int mi = 0; mi < 2; mi++) {
        float r[4];
        upk2(acc[mi][0], r[0], r[1]);
        upk2(acc[mi][1], r[2], r[3]);
        float* o = &O[(size_t)(mb + ty * 2 + mi) * CI + nb + tx * 4];
        *reinterpret_cast<float4*>(o) =
            make_float4(r[0] * inv, r[1] * inv, r[2] * inv, r[3] * inv);
    }
}

// ---------------- launch ----------------
extern "C" void kernel_launch(void* const* d_in, const int* in_sizes, int n_in,
                              void* d_out, int out_size) {
    const float* nf = (const float*)d_in[0];
    const float* U3 = (const float*)d_in[1];
    const float* U2 = (const float*)d_in[2];
    const float* U1 = (const float*)d_in[3];
    const float* w3 = (const float*)d_in[4];
    const float* w2 = (const float*)d_in[5];
    const float* w1 = (const float*)d_in[6];
    const float* WL = (const float*)d_in[7];
    float* out = (float*)d_out;

    int B = in_sizes[0] / (CI * II);   // 4096

    p0_kernel<<<(NT3 * NK3 + 255) / 256, 256>>>(U3);
    p1_kernel<<<CI, 128>>>(U2, U1, w3, w2, w1);
    main_kernel<<<dim3(B / 512, CI), 128>>>(nf);
    lin_kernel<<<dim3(B / 32, CI / 32), 128>>>(WL, out);
}